// round 7
// baseline (speedup 1.0000x reference)
#include <cuda_runtime.h>
#include <cuda_bf16.h>
#include <math.h>
#include <stdint.h>

#define TOKS    16384
#define NEXP    256
#define KDIM    7168
#define F_TOK   9280              // tokens for fma engine
#define NF      580               // (9280/32) * 2 col-tiles
#define NM      444               // ((16384-9280)/64) * 4 col-tiles  == 148*3
#define NCHF    224               // 7168/32
#define NCHM    112               // 7168/64
#define GRID    148
#define THREADS 384

__device__ __align__(16) float g_logits[(size_t)TOKS * NEXP];
__device__ __align__(16) __nv_bfloat16 g_Blimb[3][(size_t)NEXP * KDIM];

// ---- smem layout (bytes) ---------------------------------------------------
// mma A segs: (L*2+buf)*9216                  [0, 55296)      64 rows x 144B
// mma B segs: 55296 + (L*2+buf)*9216          [55296, 110592) 64 rows x 144B
// fma As: float[2][32][36]  @110592  (9216B)
// fma Bs: float[2][32][136] @119808  (34816B)
#define MMA_B_OFF 55296
#define FMA_A_OFF 110592
#define FMA_B_OFF 119808
#define SMEM_BYTES 154624

#define BAR_FMA() asm volatile("bar.sync 1, 128;" ::: "memory")
#define BAR_MMA() asm volatile("bar.sync 2, 256;" ::: "memory")

__device__ __forceinline__ uint32_t smem_u32(const void* p) {
    uint32_t a;
    asm("{ .reg .u64 t; cvta.to.shared.u64 t, %1; cvt.u32.u64 %0, t; }" : "=r"(a) : "l"(p));
    return a;
}
__device__ __forceinline__ void cp_async16(uint32_t sdst, const void* gsrc) {
    asm volatile("cp.async.cg.shared.global [%0], [%1], 16;" :: "r"(sdst), "l"(gsrc));
}
#define CP_COMMIT() asm volatile("cp.async.commit_group;" ::: "memory")
#define CP_WAIT0()  asm volatile("cp.async.wait_group 0;" ::: "memory")

__device__ __forceinline__ void mma16816(float d[4],
                                         uint32_t a0, uint32_t a1, uint32_t a2, uint32_t a3,
                                         uint32_t b0, uint32_t b1) {
    asm volatile(
        "mma.sync.aligned.m16n8k16.row.col.f32.bf16.bf16.f32 "
        "{%0,%1,%2,%3}, {%4,%5,%6,%7}, {%8,%9}, {%0,%1,%2,%3};"
        : "+f"(d[0]), "+f"(d[1]), "+f"(d[2]), "+f"(d[3])
        : "r"(a0), "r"(a1), "r"(a2), "r"(a3), "r"(b0), "r"(b1));
}

__device__ __forceinline__ void split_pair(float v0, float v1,
                                           uint32_t& h, uint32_t& m, uint32_t& l) {
    asm("cvt.rn.bf16x2.f32 %0, %1, %2;" : "=r"(h) : "f"(v1), "f"(v0));
    float h0 = __uint_as_float(h << 16);
    float h1 = __uint_as_float(h & 0xffff0000u);
    float r0 = v0 - h0, r1 = v1 - h1;
    asm("cvt.rn.bf16x2.f32 %0, %1, %2;" : "=r"(m) : "f"(r1), "f"(r0));
    float m0 = __uint_as_float(m << 16);
    float m1 = __uint_as_float(m & 0xffff0000u);
    r0 -= m0; r1 -= m1;
    asm("cvt.rn.bf16x2.f32 %0, %1, %2;" : "=r"(l) : "f"(r1), "f"(r0));
}

union F2 { float2 f; unsigned long long u; };
__device__ __forceinline__ void ffma2(F2& d, const F2& a, const F2& b) {
    asm("fma.rn.f32x2 %0, %1, %2, %0;" : "+l"(d.u) : "l"(a.u), "l"(b.u));
}
__device__ __forceinline__ F2 bcast2(float v) {
    F2 r;
    asm("mov.b64 %0, {%1, %1};" : "=l"(r.u) : "f"(v));
    return r;
}

// ---------------------------------------------------------------------------
__global__ void gate_bconv_kernel(const float* __restrict__ W) {
    int i = blockIdx.x * blockDim.x + threadIdx.x;
    if (i >= NEXP * KDIM) return;
    float v = W[i];
    __nv_bfloat16 h = __float2bfloat16_rn(v);
    float r1 = v - __bfloat162float(h);
    __nv_bfloat16 m = __float2bfloat16_rn(r1);
    float r2 = r1 - __bfloat162float(m);
    g_Blimb[0][i] = h;
    g_Blimb[1][i] = m;
    g_Blimb[2][i] = __float2bfloat16_rn(r2);
}

// ---------------------------------------------------------------------------
// Hybrid persistent kernel: warps 0-3 FFMA2 engine, warps 4-11 mma engine
// ---------------------------------------------------------------------------
__global__ __launch_bounds__(THREADS, 1)
void gate_hybrid(const float* __restrict__ X, const float* __restrict__ W) {
    extern __shared__ char smem[];
    const int tid = threadIdx.x;

    if (tid < 128) {
        // ================= FFMA2 engine: 32 tok x 128 exp tiles =================
        const int tf = tid;
        float* fAs = (float*)(smem + FMA_A_OFF);   // [2][32][36]
        float* fBs = (float*)(smem + FMA_B_OFF);   // [2][32][136]
        const int arow = tf >> 2;
        const int acol = (tf & 3) * 8;
        const int ty = (tf >> 4) * 4;
        const int tx = (tf & 15) * 8;

        for (int tile = blockIdx.x; tile < NF; tile += GRID) {
            const int t0 = (tile >> 1) * 32;
            const int e0 = (tile & 1) * 128;
            const float* aLg = X + (size_t)(t0 + arow) * KDIM + acol;
            const float* bLg = W + (size_t)(e0 + tf) * KDIM;

            F2 acc2[2][8];
            #pragma unroll
            for (int i = 0; i < 2; i++)
                #pragma unroll
                for (int j = 0; j < 8; j++) { acc2[i][j].f.x = 0.f; acc2[i][j].f.y = 0.f; }

            float4 pa[2], pb[8];
            auto ldg = [&](int kt) {
                const float4* ap = (const float4*)(aLg + kt * 32);
                pa[0] = ap[0]; pa[1] = ap[1];
                const float4* bp = (const float4*)(bLg + kt * 32);
                #pragma unroll
                for (int q = 0; q < 8; q++) pb[q] = bp[q];
            };
            auto sts = [&](int buf) {
                float* A = fAs + buf * (32 * 36);
                float* B = fBs + buf * (32 * 136);
                #pragma unroll
                for (int q = 0; q < 2; q++) {
                    A[(acol + q * 4 + 0) * 36 + arow] = pa[q].x;
                    A[(acol + q * 4 + 1) * 36 + arow] = pa[q].y;
                    A[(acol + q * 4 + 2) * 36 + arow] = pa[q].z;
                    A[(acol + q * 4 + 3) * 36 + arow] = pa[q].w;
                }
                #pragma unroll
                for (int q = 0; q < 8; q++) {
                    B[(q * 4 + 0) * 136 + tf] = pb[q].x;
                    B[(q * 4 + 1) * 136 + tf] = pb[q].y;
                    B[(q * 4 + 2) * 136 + tf] = pb[q].z;
                    B[(q * 4 + 3) * 136 + tf] = pb[q].w;
                }
            };

            ldg(0);
            sts(0);
            BAR_FMA();

            for (int kt = 0; kt < NCHF; kt++) {
                const int buf = kt & 1;
                if (kt + 1 < NCHF) ldg(kt + 1);

                const float* A = fAs + buf * (32 * 36);
                const float* B = fBs + buf * (32 * 136);
                #pragma unroll 8
                for (int k = 0; k < 32; k++) {
                    float4 av  = *(const float4*)(A + k * 36 + ty);
                    float4 bv0 = *(const float4*)(B + k * 136 + tx);
                    float4 bv1 = *(const float4*)(B + k * 136 + tx + 4);
                    F2 a2[2];
                    a2[0].f = make_float2(av.x, av.y);
                    a2[1].f = make_float2(av.z, av.w);
                    F2 bb[8];
                    bb[0] = bcast2(bv0.x); bb[1] = bcast2(bv0.y);
                    bb[2] = bcast2(bv0.z); bb[3] = bcast2(bv0.w);
                    bb[4] = bcast2(bv1.x); bb[5] = bcast2(bv1.y);
                    bb[6] = bcast2(bv1.z); bb[7] = bcast2(bv1.w);
                    #pragma unroll
                    for (int i = 0; i < 2; i++)
                        #pragma unroll
                        for (int j = 0; j < 8; j++)
                            ffma2(acc2[i][j], a2[i], bb[j]);
                }
                if (kt + 1 < NCHF) sts(1 - buf);
                BAR_FMA();
            }

            #pragma unroll
            for (int i = 0; i < 2; i++) {
                const int r = t0 + ty + 2 * i;
                float* o0 = g_logits + (size_t)r * NEXP + e0 + tx;
                float* o1 = o0 + NEXP;
                *(float4*)(o0)     = make_float4(acc2[i][0].f.x, acc2[i][1].f.x, acc2[i][2].f.x, acc2[i][3].f.x);
                *(float4*)(o0 + 4) = make_float4(acc2[i][4].f.x, acc2[i][5].f.x, acc2[i][6].f.x, acc2[i][7].f.x);
                *(float4*)(o1)     = make_float4(acc2[i][0].f.y, acc2[i][1].f.y, acc2[i][2].f.y, acc2[i][3].f.y);
                *(float4*)(o1 + 4) = make_float4(acc2[i][4].f.y, acc2[i][5].f.y, acc2[i][6].f.y, acc2[i][7].f.y);
            }
        }
        return;
    }

    // ================= mma.sync engine: 64 tok x 64 exp tiles =================
    {
        const int tid2 = tid - 128;          // 0..255
        const int lane = tid2 & 31;
        const int wid2 = tid2 >> 5;          // 0..7
        const int wm   = wid2 & 1;           // 2 m-tiles of 32 rows
        const int wn   = wid2 >> 1;          // 4 n-tiles of 16 cols
        const int g    = lane >> 2;
        const int t    = lane & 3;
        const uint32_t sbu = smem_u32(smem);

        const int arow = tid2 >> 2;          // 0..63
        const int akq  = (tid2 & 3) * 16;
        const uint32_t asts = (uint32_t)arow * 144 + (uint32_t)akq * 2;

        for (int tile = blockIdx.x; tile < NM; tile += GRID) {
            const int t0 = F_TOK + (tile >> 2) * 64;
            const int n0 = (tile & 3) * 64;
            const float* agp = X + (size_t)(t0 + arow) * KDIM + akq;

            float acc_hh[2][2][4], acc_cr[2][2][4], tot[2][2][4];
            #pragma unroll
            for (int i = 0; i < 2; i++)
                #pragma unroll
                for (int j = 0; j < 2; j++)
                    #pragma unroll
                    for (int q = 0; q < 4; q++) {
                        acc_hh[i][j][q] = 0.f; acc_cr[i][j][q] = 0.f; tot[i][j][q] = 0.f;
                    }

            float4 af[4];
            auto load_a_regs = [&](int kt) {
                const float4* p = (const float4*)(agp + kt * 64);
                #pragma unroll
                for (int i = 0; i < 4; i++) af[i] = p[i];
            };
            auto issue_b = [&](int kt, int buf) {
                #pragma unroll
                for (int L = 0; L < 3; L++) {
                    const __nv_bfloat16* gB = g_Blimb[L] + (size_t)n0 * KDIM + kt * 64;
                    uint32_t sB = sbu + MMA_B_OFF + (uint32_t)(L * 2 + buf) * 9216;
                    #pragma unroll
                    for (int q = 0; q < 2; q++) {
                        int line = q * 256 + tid2;
                        int row  = line >> 3, col = line & 7;
                        cp_async16(sB + (uint32_t)row * 144 + (uint32_t)col * 16,
                                   gB + (size_t)row * KDIM + col * 8);
                    }
                }
            };
            auto sts_a = [&](int buf) {
                const float* v = (const float*)af;
                uint32_t ph[8], pm[8], pl[8];
                #pragma unroll
                for (int i = 0; i < 8; i++)
                    split_pair(v[2 * i], v[2 * i + 1], ph[i], pm[i], pl[i]);
                char* s0 = smem + (0 * 2 + buf) * 9216;
                char* s1 = smem + (1 * 2 + buf) * 9216;
                char* s2 = smem + (2 * 2 + buf) * 9216;
                *(uint4*)(s0 + asts)      = make_uint4(ph[0], ph[1], ph[2], ph[3]);
                *(uint4*)(s0 + asts + 16) = make_uint4(ph[4], ph[5], ph[6], ph[7]);
                *(uint4*)(s1 + asts)      = make_uint4(pm[0], pm[1], pm[2], pm[3]);
                *(uint4*)(s1 + asts + 16) = make_uint4(pm[4], pm[5], pm[6], pm[7]);
                *(uint4*)(s2 + asts)      = make_uint4(pl[0], pl[1], pl[2], pl[3]);
                *(uint4*)(s2 + asts + 16) = make_uint4(pl[4], pl[5], pl[6], pl[7]);
            };

            load_a_regs(0);
            issue_b(0, 0);
            CP_COMMIT();
            sts_a(0);
            CP_WAIT0();
            BAR_MMA();

            for (int kt = 0; kt < NCHM; kt++) {
                const int buf = kt & 1;
                if (kt + 1 < NCHM) {
                    load_a_regs(kt + 1);
                    issue_b(kt + 1, 1 - buf);
                    CP_COMMIT();
                }

                const char* sA0 = smem + (0 * 2 + buf) * 9216;
                const char* sA1 = smem + (1 * 2 + buf) * 9216;
                const char* sA2 = smem + (2 * 2 + buf) * 9216;
                const char* sB0 = smem + MMA_B_OFF + (0 * 2 + buf) * 9216;
                const char* sB1 = smem + MMA_B_OFF + (1 * 2 + buf) * 9216;
                const char* sB2 = smem + MMA_B_OFF + (2 * 2 + buf) * 9216;

                #pragma unroll
                for (int ks = 0; ks < 4; ks++) {
                    const uint32_t kb0 = (uint32_t)(ks * 16 + 2 * t) * 2;
                    const uint32_t kb1 = kb0 + 16;

                    uint32_t Ah[2][4], Am[2][4], Al[2][4];
                    #pragma unroll
                    for (int m2 = 0; m2 < 2; m2++) {
                        const uint32_t r0 = (uint32_t)(wm * 32 + m2 * 16 + g) * 144;
                        const uint32_t r8 = r0 + 8 * 144;
                        Ah[m2][0] = *(const uint32_t*)(sA0 + r0 + kb0);
                        Ah[m2][1] = *(const uint32_t*)(sA0 + r8 + kb0);
                        Ah[m2][2] = *(const uint32_t*)(sA0 + r0 + kb1);
                        Ah[m2][3] = *(const uint32_t*)(sA0 + r8 + kb1);
                        Am[m2][0] = *(const uint32_t*)(sA1 + r0 + kb0);
                        Am[m2][1] = *(const uint32_t*)(sA1 + r8 + kb0);
                        Am[m2][2] = *(const uint32_t*)(sA1 + r0 + kb1);
                        Am[m2][3] = *(const uint32_t*)(sA1 + r8 + kb1);
                        Al[m2][0] = *(const uint32_t*)(sA2 + r0 + kb0);
                        Al[m2][1] = *(const uint32_t*)(sA2 + r8 + kb0);
                        Al[m2][2] = *(const uint32_t*)(sA2 + r0 + kb1);
                        Al[m2][3] = *(const uint32_t*)(sA2 + r8 + kb1);
                    }
                    uint32_t Bh[2][2], Bm[2][2], Bl[2][2];
                    #pragma unroll
                    for (int n4 = 0; n4 < 2; n4++) {
                        const uint32_t rn = (uint32_t)(wn * 16 + n4 * 8 + g) * 144;
                        Bh[n4][0] = *(const uint32_t*)(sB0 + rn + kb0);
                        Bh[n4][1] = *(const uint32_t*)(sB0 + rn + kb1);
                        Bm[n4][0] = *(const uint32_t*)(sB1 + rn + kb0);
                        Bm[n4][1] = *(const uint32_t*)(sB1 + rn + kb1);
                        Bl[n4][0] = *(const uint32_t*)(sB2 + rn + kb0);
                        Bl[n4][1] = *(const uint32_t*)(sB2 + rn + kb1);
                    }
                    #pragma unroll
                    for (int m2 = 0; m2 < 2; m2++) {
                        #pragma unroll
                        for (int n4 = 0; n4 < 2; n4++) {
                            mma16816(acc_hh[m2][n4], Ah[m2][0], Ah[m2][1], Ah[m2][2], Ah[m2][3],
                                     Bh[n4][0], Bh[n4][1]);
                            mma16816(acc_cr[m2][n4], Ah[m2][0], Ah[m2][1], Ah[m2][2], Ah[m2][3],
                                     Bm[n4][0], Bm[n4][1]);
                            mma16816(acc_cr[m2][n4], Am[m2][0], Am[m2][1], Am[m2][2], Am[m2][3],
                                     Bh[n4][0], Bh[n4][1]);
                            mma16816(acc_cr[m2][n4], Am[m2][0], Am[m2][1], Am[m2][2], Am[m2][3],
                                     Bm[n4][0], Bm[n4][1]);
                            mma16816(acc_cr[m2][n4], Ah[m2][0], Ah[m2][1], Ah[m2][2], Ah[m2][3],
                                     Bl[n4][0], Bl[n4][1]);
                            mma16816(acc_cr[m2][n4], Al[m2][0], Al[m2][1], Al[m2][2], Al[m2][3],
                                     Bh[n4][0], Bh[n4][1]);
                        }
                    }
                }

                if (kt + 1 < NCHM) sts_a(1 - buf);
                CP_WAIT0();
                BAR_MMA();

                if ((kt & 31) == 31) {
                    #pragma unroll
                    for (int m2 = 0; m2 < 2; m2++)
                        #pragma unroll
                        for (int n4 = 0; n4 < 2; n4++)
                            #pragma unroll
                            for (int q = 0; q < 4; q++) {
                                tot[m2][n4][q] += acc_hh[m2][n4][q];
                                acc_hh[m2][n4][q] = 0.f;
                            }
                }
            }

            #pragma unroll
            for (int m2 = 0; m2 < 2; m2++) {
                #pragma unroll
                for (int n4 = 0; n4 < 2; n4++) {
                    float f0 = (tot[m2][n4][0] + acc_hh[m2][n4][0]) + acc_cr[m2][n4][0];
                    float f1 = (tot[m2][n4][1] + acc_hh[m2][n4][1]) + acc_cr[m2][n4][1];
                    float f2 = (tot[m2][n4][2] + acc_hh[m2][n4][2]) + acc_cr[m2][n4][2];
                    float f3 = (tot[m2][n4][3] + acc_hh[m2][n4][3]) + acc_cr[m2][n4][3];
                    const int row = t0 + wm * 32 + m2 * 16 + g;
                    const int col = n0 + wn * 16 + n4 * 8 + 2 * t;
                    *(float2*)(g_logits + (size_t)row * NEXP + col)       = make_float2(f0, f1);
                    *(float2*)(g_logits + (size_t)(row + 8) * NEXP + col) = make_float2(f2, f3);
                }
            }
        }
    }
}

// ---------------------------------------------------------------------------
// Routing: one warp per token (validated rounds 2-5)
// ---------------------------------------------------------------------------
__global__ void gate_route_kernel(const float* __restrict__ bias,
                                  float* __restrict__ out_w,
                                  float* __restrict__ out_i,
                                  int Tn) {
    const int warp = (blockIdx.x * blockDim.x + threadIdx.x) >> 5;
    if (warp >= Tn) return;
    const int lane = threadIdx.x & 31;
    const unsigned FULL = 0xffffffffu;

    const float* row = g_logits + (size_t)warp * NEXP;
    float4 v0 = *(const float4*)(row + lane * 8);
    float4 v1 = *(const float4*)(row + lane * 8 + 4);
    float zz[8] = {v0.x, v0.y, v0.z, v0.w, v1.x, v1.y, v1.z, v1.w};

    float sc[8], sb8[8];
    #pragma unroll
    for (int j = 0; j < 8; j++) {
        float s = 1.0f / (1.0f + expf(-zz[j]));
        sc[j]  = s;
        sb8[j] = s + bias[lane * 8 + j];
    }

    float m1 = -INFINITY, m2 = -INFINITY;
    #pragma unroll
    for (int j = 0; j < 8; j++) {
        float v = sb8[j];
        if (v > m1) { m2 = m1; m1 = v; }
        else if (v > m2) { m2 = v; }
    }
    #pragma unroll
    for (int off = 1; off <= 2; off <<= 1) {
        float o1 = __shfl_xor_sync(FULL, m1, off);
        float o2 = __shfl_xor_sync(FULL, m2, off);
        if (o1 > m1) { m2 = fmaxf(m1, o2); m1 = o1; }
        else         { m2 = fmaxf(m2, o1); }
    }
    float gsum = m1 + m2;

    float gs[8];
    #pragma unroll
    for (int gI = 0; gI < 8; gI++) gs[gI] = __shfl_sync(FULL, gsum, gI * 4);

    int chosen = 0;
    #pragma unroll
    for (int it = 0; it < 4; it++) {
        float best = -INFINITY; int bg = 0;
        #pragma unroll
        for (int gI = 0; gI < 8; gI++) {
            if (!((chosen >> gI) & 1) && gs[gI] > best) { best = gs[gI]; bg = gI; }
        }
        chosen |= 1 << bg;
    }
    const bool kept = (chosen >> (lane >> 2)) & 1;

    float v[8];
    #pragma unroll
    for (int j = 0; j < 8; j++) v[j] = kept ? sb8[j] : -INFINITY;

    float my_w = 0.0f; int my_i = 0;
    float wsum = 0.0f;

    #pragma unroll
    for (int it = 0; it < 8; it++) {
        float bv = -INFINITY; int bi = 0x7fffffff; float bsco = 0.0f;
        #pragma unroll
        for (int j = 0; j < 8; j++) {
            if (v[j] > bv) { bv = v[j]; bi = lane * 8 + j; bsco = sc[j]; }
        }
        #pragma unroll
        for (int off = 16; off; off >>= 1) {
            float ov = __shfl_xor_sync(FULL, bv, off);
            int   oi = __shfl_xor_sync(FULL, bi, off);
            float os = __shfl_xor_sync(FULL, bsco, off);
            if (ov > bv || (ov == bv && oi < bi)) { bv = ov; bi = oi; bsco = os; }
        }
        if (lane == it) { my_w = bsco; my_i = bi; }
        if ((bi >> 3) == lane) v[bi & 7] = -INFINITY;
        wsum += bsco;
    }

    if (lane < 8) {
        out_w[(size_t)warp * 8 + lane] = (my_w / wsum) * 2.5f;
        out_i[(size_t)warp * 8 + lane] = (float)my_i;
    }
}

// ---------------------------------------------------------------------------
extern "C" void kernel_launch(void* const* d_in, const int* in_sizes, int n_in,
                              void* d_out, int out_size) {
    const float* x    = (const float*)d_in[0];   // [T, 7168]
    const float* w    = (const float*)d_in[1];   // [256, 7168]
    const float* bias = (const float*)d_in[2];   // [256]

    const int Tn = in_sizes[0] / KDIM;

    cudaFuncSetAttribute(gate_hybrid,
                         cudaFuncAttributeMaxDynamicSharedMemorySize, SMEM_BYTES);

    gate_bconv_kernel<<<(NEXP * KDIM + 255) / 256, 256>>>(w);

    gate_hybrid<<<GRID, THREADS, SMEM_BYTES>>>(x, w);

    float* out_w = (float*)d_out;
    float* out_i = (float*)d_out + (size_t)Tn * 8;
    const int warps_per_block = 8;
    const int blocks = (Tn + warps_per_block - 1) / warps_per_block;
    gate_route_kernel<<<blocks, warps_per_block * 32>>>(bias, out_w, out_i, Tn);
}

// round 8
// speedup vs baseline: 1.7762x; 1.7762x over previous
#include <cuda_runtime.h>
#include <cuda_fp16.h>
#include <math.h>
#include <stdint.h>

#define TOKS    16384
#define NEXP    256
#define KDIM    7168
#define BM      128
#define BN      64
#define BK      64
#define NCH     (KDIM / BK)     // 112
#define THREADS 256

__device__ __align__(16) float g_logits[(size_t)TOKS * NEXP];
__device__ __align__(16) __half g_Wlimb[2][(size_t)NEXP * KDIM];

// ---- smem layout (bytes), fp16 with 144B row stride ------------------------
// A segs: (L*2+buf)*18432 + row*144 + k*2   rows 0..127   [0, 73728)
// B segs: 73728 + (L*2+buf)*9216            rows 0..63    [73728, 110592)
#define SA_SEG   18432
#define SB_BASE  73728
#define SB_SEG   9216
#define SMEM_BYTES 110592

__device__ __forceinline__ uint32_t smem_u32(const void* p) {
    uint32_t a;
    asm("{ .reg .u64 t; cvta.to.shared.u64 t, %1; cvt.u32.u64 %0, t; }" : "=r"(a) : "l"(p));
    return a;
}
__device__ __forceinline__ void cp_async16(uint32_t sdst, const void* gsrc) {
    asm volatile("cp.async.cg.shared.global [%0], [%1], 16;" :: "r"(sdst), "l"(gsrc));
}
#define CP_COMMIT() asm volatile("cp.async.commit_group;" ::: "memory")
#define CP_WAIT0()  asm volatile("cp.async.wait_group 0;" ::: "memory")

__device__ __forceinline__ void mma16816(float d[4],
                                         uint32_t a0, uint32_t a1, uint32_t a2, uint32_t a3,
                                         uint32_t b0, uint32_t b1) {
    asm volatile(
        "mma.sync.aligned.m16n8k16.row.col.f32.f16.f16.f32 "
        "{%0,%1,%2,%3}, {%4,%5,%6,%7}, {%8,%9}, {%0,%1,%2,%3};"
        : "+f"(d[0]), "+f"(d[1]), "+f"(d[2]), "+f"(d[3])
        : "r"(a0), "r"(a1), "r"(a2), "r"(a3), "r"(b0), "r"(b1));
}

// split fp32 pair (scaled x64) into 2 packed fp16x2 limbs
__device__ __forceinline__ void split_pair(float v0, float v1,
                                           uint32_t& h, uint32_t& m) {
    v0 *= 64.0f; v1 *= 64.0f;
    __half2 h2 = __floats2half2_rn(v0, v1);
    h = *reinterpret_cast<uint32_t*>(&h2);
    float2 hf = __half22float2(h2);
    __half2 m2 = __floats2half2_rn(v0 - hf.x, v1 - hf.y);
    m = *reinterpret_cast<uint32_t*>(&m2);
}

// ---------------------------------------------------------------------------
// W limb pre-conversion: w*64 -> h + m (fp16 limbs)
// ---------------------------------------------------------------------------
__global__ void gate_wconv_kernel(const float* __restrict__ W) {
    int i = blockIdx.x * blockDim.x + threadIdx.x;
    if (i >= NEXP * KDIM) return;
    float v = W[i] * 64.0f;
    __half h = __float2half_rn(v);
    float r = v - __half2float(h);
    g_Wlimb[0][i] = h;
    g_Wlimb[1][i] = __float2half_rn(r);
}

// ---------------------------------------------------------------------------
// mma.sync fp16 2-limb / 3-product GEMM: logits[t,n] = x[t,:] . W[n,:]
// ---------------------------------------------------------------------------
__global__ __launch_bounds__(THREADS, 1)
void gate_mma_gemm(const float* __restrict__ X) {
    extern __shared__ char smem[];
    const uint32_t sbu = smem_u32(smem);

    const int tid  = threadIdx.x;
    const int lane = tid & 31;
    const int wid  = tid >> 5;
    const int wm   = wid & 3;        // warp row 0..3  (32 tokens each)
    const int wn   = wid >> 2;       // warp col 0..1  (32 experts each)
    const int g    = lane >> 2;
    const int t    = lane & 3;

    const int bn = blockIdx.x;
    const int bm = blockIdx.y;
    const int t0 = bm * BM;
    const int n0 = bn * BN;

    // A gmem loader: thread -> (row, 32-k half)
    const int arow = tid >> 1;
    const int akh  = (tid & 1) * 32;
    const float* agp = X + (size_t)(t0 + arow) * KDIM + akh;
    const uint32_t asts = (uint32_t)arow * 144 + (uint32_t)akh * 2;

    float acc_hh[2][4][4], acc_cr[2][4][4], tot[2][4][4];
    #pragma unroll
    for (int i = 0; i < 2; i++)
        #pragma unroll
        for (int j = 0; j < 4; j++)
            #pragma unroll
            for (int q = 0; q < 4; q++) {
                acc_hh[i][j][q] = 0.0f; acc_cr[i][j][q] = 0.0f; tot[i][j][q] = 0.0f;
            }

    float4 af[8];

    auto load_a_regs = [&](int kt) {
        const float4* p = (const float4*)(agp + kt * BK);
        #pragma unroll
        for (int i = 0; i < 8; i++) af[i] = p[i];
    };
    auto issue_b = [&](int kt, int buf) {
        #pragma unroll
        for (int L = 0; L < 2; L++) {
            const __half* gB = g_Wlimb[L] + (size_t)n0 * KDIM + kt * BK;
            uint32_t sB = sbu + SB_BASE + (uint32_t)(L * 2 + buf) * SB_SEG;
            #pragma unroll
            for (int q = 0; q < 2; q++) {
                int line = q * 256 + tid;
                int row  = line >> 3, c = line & 7;
                cp_async16(sB + (uint32_t)row * 144 + (uint32_t)c * 16,
                           gB + (size_t)row * KDIM + c * 8);
            }
        }
    };
    auto sts_a = [&](int buf) {
        const float* v = (const float*)af;
        uint32_t ph[16], pm[16];
        #pragma unroll
        for (int i = 0; i < 16; i++)
            split_pair(v[2 * i], v[2 * i + 1], ph[i], pm[i]);
        char* s0 = smem + (0 * 2 + buf) * SA_SEG;
        char* s1 = smem + (1 * 2 + buf) * SA_SEG;
        #pragma unroll
        for (int c = 0; c < 4; c++) {
            uint32_t off = asts + (uint32_t)c * 16;
            *(uint4*)(s0 + off) = make_uint4(ph[4*c], ph[4*c+1], ph[4*c+2], ph[4*c+3]);
            *(uint4*)(s1 + off) = make_uint4(pm[4*c], pm[4*c+1], pm[4*c+2], pm[4*c+3]);
        }
    };

    // ---- prologue: chunk 0 ----
    load_a_regs(0);
    issue_b(0, 0);
    CP_COMMIT();
    sts_a(0);
    CP_WAIT0();
    __syncthreads();

    for (int kt = 0; kt < NCH; kt++) {
        const int buf = kt & 1;
        if (kt + 1 < NCH) {
            load_a_regs(kt + 1);
            issue_b(kt + 1, 1 - buf);
            CP_COMMIT();
        }

        const char* sA0 = smem + (0 * 2 + buf) * SA_SEG;
        const char* sA1 = smem + (1 * 2 + buf) * SA_SEG;
        const char* sB0 = smem + SB_BASE + (0 * 2 + buf) * SB_SEG;
        const char* sB1 = smem + SB_BASE + (1 * 2 + buf) * SB_SEG;

        #pragma unroll
        for (int ks = 0; ks < 4; ks++) {
            const uint32_t kb0 = (uint32_t)(ks * 16 + 2 * t) * 2;
            const uint32_t kb1 = kb0 + 16;

            uint32_t Ah[2][4], Am[2][4];
            #pragma unroll
            for (int m2 = 0; m2 < 2; m2++) {
                const uint32_t r0 = (uint32_t)(wm * 32 + m2 * 16 + g) * 144;
                const uint32_t r8 = r0 + 8 * 144;
                Ah[m2][0] = *(const uint32_t*)(sA0 + r0 + kb0);
                Ah[m2][1] = *(const uint32_t*)(sA0 + r8 + kb0);
                Ah[m2][2] = *(const uint32_t*)(sA0 + r0 + kb1);
                Ah[m2][3] = *(const uint32_t*)(sA0 + r8 + kb1);
                Am[m2][0] = *(const uint32_t*)(sA1 + r0 + kb0);
                Am[m2][1] = *(const uint32_t*)(sA1 + r8 + kb0);
                Am[m2][2] = *(const uint32_t*)(sA1 + r0 + kb1);
                Am[m2][3] = *(const uint32_t*)(sA1 + r8 + kb1);
            }
            uint32_t Bh[4][2], Bm[4][2];
            #pragma unroll
            for (int n4 = 0; n4 < 4; n4++) {
                const uint32_t rn = (uint32_t)(wn * 32 + n4 * 8 + g) * 144;
                Bh[n4][0] = *(const uint32_t*)(sB0 + rn + kb0);
                Bh[n4][1] = *(const uint32_t*)(sB0 + rn + kb1);
                Bm[n4][0] = *(const uint32_t*)(sB1 + rn + kb0);
                Bm[n4][1] = *(const uint32_t*)(sB1 + rn + kb1);
            }
            #pragma unroll
            for (int m2 = 0; m2 < 2; m2++) {
                #pragma unroll
                for (int n4 = 0; n4 < 4; n4++) {
                    mma16816(acc_hh[m2][n4], Ah[m2][0], Ah[m2][1], Ah[m2][2], Ah[m2][3],
                             Bh[n4][0], Bh[n4][1]);
                    mma16816(acc_cr[m2][n4], Ah[m2][0], Ah[m2][1], Ah[m2][2], Ah[m2][3],
                             Bm[n4][0], Bm[n4][1]);
                    mma16816(acc_cr[m2][n4], Am[m2][0], Am[m2][1], Am[m2][2], Am[m2][3],
                             Bh[n4][0], Bh[n4][1]);
                }
            }
        }

        if (kt + 1 < NCH) sts_a(1 - buf);
        CP_WAIT0();
        __syncthreads();

        if ((kt & 31) == 31) {   // flush hh accumulators (bounds serial error)
            #pragma unroll
            for (int m2 = 0; m2 < 2; m2++)
                #pragma unroll
                for (int n4 = 0; n4 < 4; n4++)
                    #pragma unroll
                    for (int q = 0; q < 4; q++) {
                        tot[m2][n4][q] += acc_hh[m2][n4][q];
                        acc_hh[m2][n4][q] = 0.0f;
                    }
        }
    }

    // ---- epilogue: unscale by 1/(64*64) ----
    const float INV = 1.0f / 4096.0f;
    #pragma unroll
    for (int m2 = 0; m2 < 2; m2++) {
        #pragma unroll
        for (int n4 = 0; n4 < 4; n4++) {
            float f0 = ((tot[m2][n4][0] + acc_hh[m2][n4][0]) + acc_cr[m2][n4][0]) * INV;
            float f1 = ((tot[m2][n4][1] + acc_hh[m2][n4][1]) + acc_cr[m2][n4][1]) * INV;
            float f2 = ((tot[m2][n4][2] + acc_hh[m2][n4][2]) + acc_cr[m2][n4][2]) * INV;
            float f3 = ((tot[m2][n4][3] + acc_hh[m2][n4][3]) + acc_cr[m2][n4][3]) * INV;
            const int row = t0 + wm * 32 + m2 * 16 + g;
            const int col = n0 + wn * 32 + n4 * 8 + 2 * t;
            *(float2*)(g_logits + (size_t)row * NEXP + col)       = make_float2(f0, f1);
            *(float2*)(g_logits + (size_t)(row + 8) * NEXP + col) = make_float2(f2, f3);
        }
    }
}

// ---------------------------------------------------------------------------
// Routing: one warp per token (validated rounds 2-6)
// ---------------------------------------------------------------------------
__global__ void gate_route_kernel(const float* __restrict__ bias,
                                  float* __restrict__ out_w,
                                  float* __restrict__ out_i,
                                  int Tn) {
    const int warp = (blockIdx.x * blockDim.x + threadIdx.x) >> 5;
    if (warp >= Tn) return;
    const int lane = threadIdx.x & 31;
    const unsigned FULL = 0xffffffffu;

    const float* row = g_logits + (size_t)warp * NEXP;
    float4 v0 = *(const float4*)(row + lane * 8);
    float4 v1 = *(const float4*)(row + lane * 8 + 4);
    float zz[8] = {v0.x, v0.y, v0.z, v0.w, v1.x, v1.y, v1.z, v1.w};

    float sc[8], sb8[8];
    #pragma unroll
    for (int j = 0; j < 8; j++) {
        float s = 1.0f / (1.0f + expf(-zz[j]));
        sc[j]  = s;
        sb8[j] = s + bias[lane * 8 + j];
    }

    float m1 = -INFINITY, m2 = -INFINITY;
    #pragma unroll
    for (int j = 0; j < 8; j++) {
        float v = sb8[j];
        if (v > m1) { m2 = m1; m1 = v; }
        else if (v > m2) { m2 = v; }
    }
    #pragma unroll
    for (int off = 1; off <= 2; off <<= 1) {
        float o1 = __shfl_xor_sync(FULL, m1, off);
        float o2 = __shfl_xor_sync(FULL, m2, off);
        if (o1 > m1) { m2 = fmaxf(m1, o2); m1 = o1; }
        else         { m2 = fmaxf(m2, o1); }
    }
    float gsum = m1 + m2;

    float gs[8];
    #pragma unroll
    for (int gI = 0; gI < 8; gI++) gs[gI] = __shfl_sync(FULL, gsum, gI * 4);

    int chosen = 0;
    #pragma unroll
    for (int it = 0; it < 4; it++) {
        float best = -INFINITY; int bg = 0;
        #pragma unroll
        for (int gI = 0; gI < 8; gI++) {
            if (!((chosen >> gI) & 1) && gs[gI] > best) { best = gs[gI]; bg = gI; }
        }
        chosen |= 1 << bg;
    }
    const bool kept = (chosen >> (lane >> 2)) & 1;

    float v[8];
    #pragma unroll
    for (int j = 0; j < 8; j++) v[j] = kept ? sb8[j] : -INFINITY;

    float my_w = 0.0f; int my_i = 0;
    float wsum = 0.0f;

    #pragma unroll
    for (int it = 0; it < 8; it++) {
        float bv = -INFINITY; int bi = 0x7fffffff; float bsco = 0.0f;
        #pragma unroll
        for (int j = 0; j < 8; j++) {
            if (v[j] > bv) { bv = v[j]; bi = lane * 8 + j; bsco = sc[j]; }
        }
        #pragma unroll
        for (int off = 16; off; off >>= 1) {
            float ov = __shfl_xor_sync(FULL, bv, off);
            int   oi = __shfl_xor_sync(FULL, bi, off);
            float os = __shfl_xor_sync(FULL, bsco, off);
            if (ov > bv || (ov == bv && oi < bi)) { bv = ov; bi = oi; bsco = os; }
        }
        if (lane == it) { my_w = bsco; my_i = bi; }
        if ((bi >> 3) == lane) v[bi & 7] = -INFINITY;
        wsum += bsco;
    }

    if (lane < 8) {
        out_w[(size_t)warp * 8 + lane] = (my_w / wsum) * 2.5f;
        out_i[(size_t)warp * 8 + lane] = (float)my_i;
    }
}

// ---------------------------------------------------------------------------
extern "C" void kernel_launch(void* const* d_in, const int* in_sizes, int n_in,
                              void* d_out, int out_size) {
    const float* x    = (const float*)d_in[0];   // [T, 7168]
    const float* w    = (const float*)d_in[1];   // [256, 7168]
    const float* bias = (const float*)d_in[2];   // [256]

    const int Tn = in_sizes[0] / KDIM;

    cudaFuncSetAttribute(gate_mma_gemm,
                         cudaFuncAttributeMaxDynamicSharedMemorySize, SMEM_BYTES);

    gate_wconv_kernel<<<(NEXP * KDIM + 255) / 256, 256>>>(w);

    dim3 grid(NEXP / BN, Tn / BM);   // (4, 128), bn fastest -> x L2 reuse
    gate_mma_gemm<<<grid, THREADS, SMEM_BYTES>>>(x);

    float* out_w = (float*)d_out;
    float* out_i = (float*)d_out + (size_t)Tn * 8;
    const int warps_per_block = 8;
    const int blocks = (Tn + warps_per_block - 1) / warps_per_block;
    gate_route_kernel<<<blocks, warps_per_block * 32>>>(bias, out_w, out_i, Tn);
}

// round 15
// speedup vs baseline: 2.7338x; 1.5391x over previous
#include <cuda_runtime.h>
#include <cuda_fp16.h>
#include <math.h>
#include <stdint.h>

#define TOKS    16384
#define NEXP    256
#define KDIM    7168
#define BM      128
#define BN      64
#define BK      64
#define NCH     (KDIM / BK)     // 112
#define THREADS 256

__device__ __align__(16) float  g_logits[(size_t)TOKS * NEXP];
__device__ __align__(16) __half g_Wlimb[2][(size_t)NEXP * KDIM];
__device__ __align__(16) __half g_Alimb[2][(size_t)TOKS * KDIM];

// ---- smem (bytes), fp16, 144B row stride, 3 stages -------------------------
// A: stage*36864 + L*18432 + row*144 + k*2      rows 0..127   [0, 110592)
// B: 110592 + stage*18432 + L*9216 + row*144    rows 0..63    [110592, 165888)
#define SA_STG  36864
#define SA_L    18432
#define SB_BASE 110592
#define SB_STG  18432
#define SB_L    9216
#define SMEM_BYTES 165888

__device__ __forceinline__ uint32_t smem_u32(const void* p) {
    uint32_t a;
    asm("{ .reg .u64 t; cvta.to.shared.u64 t, %1; cvt.u32.u64 %0, t; }" : "=r"(a) : "l"(p));
    return a;
}
__device__ __forceinline__ void cp_async16(uint32_t sdst, const void* gsrc) {
    asm volatile("cp.async.cg.shared.global [%0], [%1], 16;" :: "r"(sdst), "l"(gsrc));
}
#define CP_COMMIT() asm volatile("cp.async.commit_group;" ::: "memory")
#define CP_WAIT0()  asm volatile("cp.async.wait_group 0;" ::: "memory")
#define CP_WAIT1()  asm volatile("cp.async.wait_group 1;" ::: "memory")

#define LDM4(r0, r1, r2, r3, addr) \
    asm volatile("ldmatrix.sync.aligned.m8n8.x4.shared.b16 {%0,%1,%2,%3}, [%4];" \
        : "=r"(r0), "=r"(r1), "=r"(r2), "=r"(r3) : "r"(addr))

__device__ __forceinline__ void mma16816(float d[4],
                                         uint32_t a0, uint32_t a1, uint32_t a2, uint32_t a3,
                                         uint32_t b0, uint32_t b1) {
    asm volatile(
        "mma.sync.aligned.m16n8k16.row.col.f32.f16.f16.f32 "
        "{%0,%1,%2,%3}, {%4,%5,%6,%7}, {%8,%9}, {%0,%1,%2,%3};"
        : "+f"(d[0]), "+f"(d[1]), "+f"(d[2]), "+f"(d[3])
        : "r"(a0), "r"(a1), "r"(a2), "r"(a3), "r"(b0), "r"(b1));
}

// split fp32 pair (scaled x64) into 2 packed fp16x2 limbs
__device__ __forceinline__ void split_pair(float v0, float v1,
                                           uint32_t& h, uint32_t& m) {
    v0 *= 64.0f; v1 *= 64.0f;
    __half2 h2 = __floats2half2_rn(v0, v1);
    h = *reinterpret_cast<uint32_t*>(&h2);
    float2 hf = __half22float2(h2);
    __half2 m2 = __floats2half2_rn(v0 - hf.x, v1 - hf.y);
    m = *reinterpret_cast<uint32_t*>(&m2);
}

// ---------------------------------------------------------------------------
__global__ void gate_wconv_kernel(const float* __restrict__ W) {
    int i = blockIdx.x * blockDim.x + threadIdx.x;
    if (i >= NEXP * KDIM) return;
    float v = W[i] * 64.0f;
    __half h = __float2half_rn(v);
    float r = v - __half2float(h);
    g_Wlimb[0][i] = h;
    g_Wlimb[1][i] = __float2half_rn(r);
}

__global__ void gate_aconv_kernel(const float* __restrict__ X) {
    size_t i = ((size_t)blockIdx.x * blockDim.x + threadIdx.x) * 4;
    if (i >= (size_t)TOKS * KDIM) return;
    float4 v = *(const float4*)(X + i);
    uint32_t h0, m0, h1, m1;
    split_pair(v.x, v.y, h0, m0);
    split_pair(v.z, v.w, h1, m1);
    *(uint2*)((char*)g_Alimb[0] + i * 2) = make_uint2(h0, h1);
    *(uint2*)((char*)g_Alimb[1] + i * 2) = make_uint2(m0, m1);
}

// ---------------------------------------------------------------------------
// mma.sync fp16 2-limb / 3-product GEMM, cp.async 3-stage + ldmatrix
// ---------------------------------------------------------------------------
__global__ __launch_bounds__(THREADS)
void gate_mma_gemm() {
    extern __shared__ char smem[];
    const uint32_t sbu = smem_u32(smem);

    const int tid  = threadIdx.x;
    const int lane = tid & 31;
    const int wid  = tid >> 5;
    const int wm   = wid & 3;        // warp row 0..3  (32 tokens)
    const int wn   = wid >> 2;       // warp col 0..1  (32 experts)
    const int g    = lane >> 2;
    const int t    = lane & 3;

    const int bn = blockIdx.x;
    const int bm = blockIdx.y;
    const int t0 = bm * BM;
    const int n0 = bn * BN;

    // ldmatrix per-lane base offsets (j = matrix index, r = row within matrix)
    const int j = lane >> 3, r = lane & 7;
    const uint32_t aL = (uint32_t)((wm * 32 + (j & 1) * 8 + r) * 144 + (j >> 1) * 16);
    const uint32_t bL = (uint32_t)((wn * 32 + (j >> 1) * 8 + r) * 144 + (j & 1) * 16);

    float acc_hh[2][4][4], acc_cr[2][4][4], tot[2][4][4];
    #pragma unroll
    for (int i = 0; i < 2; i++)
        #pragma unroll
        for (int jj = 0; jj < 4; jj++)
            #pragma unroll
            for (int q = 0; q < 4; q++) {
                acc_hh[i][jj][q] = 0.0f; acc_cr[i][jj][q] = 0.0f; tot[i][jj][q] = 0.0f;
            }

    auto issue_ab = [&](int kt, int st) {
        #pragma unroll
        for (int L = 0; L < 2; L++) {
            const __half* gA = g_Alimb[L] + (size_t)t0 * KDIM + kt * BK;
            uint32_t sA = sbu + (uint32_t)st * SA_STG + (uint32_t)L * SA_L;
            #pragma unroll
            for (int q = 0; q < 4; q++) {
                int line = q * 256 + tid;
                int row  = line >> 3, c = line & 7;
                cp_async16(sA + (uint32_t)row * 144 + (uint32_t)c * 16,
                           gA + (size_t)row * KDIM + c * 8);
            }
            const __half* gB = g_Wlimb[L] + (size_t)n0 * KDIM + kt * BK;
            uint32_t sB = sbu + SB_BASE + (uint32_t)st * SB_STG + (uint32_t)L * SB_L;
            #pragma unroll
            for (int q = 0; q < 2; q++) {
                int line = q * 256 + tid;
                int row  = line >> 3, c = line & 7;
                cp_async16(sB + (uint32_t)row * 144 + (uint32_t)c * 16,
                           gB + (size_t)row * KDIM + c * 8);
            }
        }
    };

    // ---- prologue: stages 0,1 ----
    issue_ab(0, 0); CP_COMMIT();
    issue_ab(1, 1); CP_COMMIT();
    CP_WAIT1();
    __syncthreads();

    int cs = 0, ps = 2;
    for (int kt = 0; kt < NCH; kt++) {
        const bool more = (kt + 2 < NCH);
        if (more) { issue_ab(kt + 2, ps); CP_COMMIT(); }

        const uint32_t A0 = sbu + (uint32_t)cs * SA_STG + aL;
        const uint32_t A1 = A0 + SA_L;
        const uint32_t B0 = sbu + SB_BASE + (uint32_t)cs * SB_STG + bL;
        const uint32_t B1 = B0 + SB_L;

        #pragma unroll
        for (int ks = 0; ks < 4; ks++) {
            const uint32_t ko = (uint32_t)ks * 32;
            uint32_t Ah[2][4], Am[2][4], Bh[8], Bm[8];
            LDM4(Ah[0][0], Ah[0][1], Ah[0][2], Ah[0][3], A0 + ko);
            LDM4(Ah[1][0], Ah[1][1], Ah[1][2], Ah[1][3], A0 + 2304 + ko);
            LDM4(Am[0][0], Am[0][1], Am[0][2], Am[0][3], A1 + ko);
            LDM4(Am[1][0], Am[1][1], Am[1][2], Am[1][3], A1 + 2304 + ko);
            LDM4(Bh[0], Bh[1], Bh[2], Bh[3], B0 + ko);
            LDM4(Bh[4], Bh[5], Bh[6], Bh[7], B0 + 2304 + ko);
            LDM4(Bm[0], Bm[1], Bm[2], Bm[3], B1 + ko);
            LDM4(Bm[4], Bm[5], Bm[6], Bm[7], B1 + 2304 + ko);

            #pragma unroll
            for (int m2 = 0; m2 < 2; m2++)
                #pragma unroll
                for (int n4 = 0; n4 < 4; n4++)
                    mma16816(acc_hh[m2][n4], Ah[m2][0], Ah[m2][1], Ah[m2][2], Ah[m2][3],
                             Bh[2 * n4], Bh[2 * n4 + 1]);
            #pragma unroll
            for (int m2 = 0; m2 < 2; m2++)
                #pragma unroll
                for (int n4 = 0; n4 < 4; n4++)
                    mma16816(acc_cr[m2][n4], Ah[m2][0], Ah[m2][1], Ah[m2][2], Ah[m2][3],
                             Bm[2 * n4], Bm[2 * n4 + 1]);
            #pragma unroll
            for (int m2 = 0; m2 < 2; m2++)
                #pragma unroll
                for (int n4 = 0; n4 < 4; n4++)
                    mma16816(acc_cr[m2][n4], Am[m2][0], Am[m2][1], Am[m2][2], Am[m2][3],
                             Bh[2 * n4], Bh[2 * n4 + 1]);
        }

        if (more) CP_WAIT1(); else CP_WAIT0();
        __syncthreads();

        if ((kt & 31) == 31) {   // flush hh into SEPARATE tot (round-8 numerics)
            #pragma unroll
            for (int m2 = 0; m2 < 2; m2++)
                #pragma unroll
                for (int n4 = 0; n4 < 4; n4++)
                    #pragma unroll
                    for (int q = 0; q < 4; q++) {
                        tot[m2][n4][q] += acc_hh[m2][n4][q];
                        acc_hh[m2][n4][q] = 0.0f;
                    }
        }
        cs = (cs == 2) ? 0 : cs + 1;
        ps = (ps == 2) ? 0 : ps + 1;
    }

    // ---- epilogue: unscale by 1/(64*64) ----
    const float INV = 1.0f / 4096.0f;
    #pragma unroll
    for (int m2 = 0; m2 < 2; m2++) {
        #pragma unroll
        for (int n4 = 0; n4 < 4; n4++) {
            float f0 = ((tot[m2][n4][0] + acc_hh[m2][n4][0]) + acc_cr[m2][n4][0]) * INV;
            float f1 = ((tot[m2][n4][1] + acc_hh[m2][n4][1]) + acc_cr[m2][n4][1]) * INV;
            float f2 = ((tot[m2][n4][2] + acc_hh[m2][n4][2]) + acc_cr[m2][n4][2]) * INV;
            float f3 = ((tot[m2][n4][3] + acc_hh[m2][n4][3]) + acc_cr[m2][n4][3]) * INV;
            const int row = t0 + wm * 32 + m2 * 16 + g;
            const int col = n0 + wn * 32 + n4 * 8 + 2 * t;
            *(float2*)(g_logits + (size_t)row * NEXP + col)       = make_float2(f0, f1);
            *(float2*)(g_logits + (size_t)(row + 8) * NEXP + col) = make_float2(f2, f3);
        }
    }
}

// ---------------------------------------------------------------------------
// Routing: one warp per token (validated rounds 2-8)
// ---------------------------------------------------------------------------
__global__ void gate_route_kernel(const float* __restrict__ bias,
                                  float* __restrict__ out_w,
                                  float* __restrict__ out_i,
                                  int Tn) {
    const int warp = (blockIdx.x * blockDim.x + threadIdx.x) >> 5;
    if (warp >= Tn) return;
    const int lane = threadIdx.x & 31;
    const unsigned FULL = 0xffffffffu;

    const float* row = g_logits + (size_t)warp * NEXP;
    float4 v0 = *(const float4*)(row + lane * 8);
    float4 v1 = *(const float4*)(row + lane * 8 + 4);
    float zz[8] = {v0.x, v0.y, v0.z, v0.w, v1.x, v1.y, v1.z, v1.w};

    float sc[8], sb8[8];
    #pragma unroll
    for (int jj = 0; jj < 8; jj++) {
        float s = 1.0f / (1.0f + expf(-zz[jj]));
        sc[jj]  = s;
        sb8[jj] = s + bias[lane * 8 + jj];
    }

    float m1 = -INFINITY, m2 = -INFINITY;
    #pragma unroll
    for (int jj = 0; jj < 8; jj++) {
        float v = sb8[jj];
        if (v > m1) { m2 = m1; m1 = v; }
        else if (v > m2) { m2 = v; }
    }
    #pragma unroll
    for (int off = 1; off <= 2; off <<= 1) {
        float o1 = __shfl_xor_sync(FULL, m1, off);
        float o2 = __shfl_xor_sync(FULL, m2, off);
        if (o1 > m1) { m2 = fmaxf(m1, o2); m1 = o1; }
        else         { m2 = fmaxf(m2, o1); }
    }
    float gsum = m1 + m2;

    float gs[8];
    #pragma unroll
    for (int gI = 0; gI < 8; gI++) gs[gI] = __shfl_sync(FULL, gsum, gI * 4);

    int chosen = 0;
    #pragma unroll
    for (int it = 0; it < 4; it++) {
        float best = -INFINITY; int bg = 0;
        #pragma unroll
        for (int gI = 0; gI < 8; gI++) {
            if (!((chosen >> gI) & 1) && gs[gI] > best) { best = gs[gI]; bg = gI; }
        }
        chosen |= 1 << bg;
    }
    const bool kept = (chosen >> (lane >> 2)) & 1;

    float v[8];
    #pragma unroll
    for (int jj = 0; jj < 8; jj++) v[jj] = kept ? sb8[jj] : -INFINITY;

    float my_w = 0.0f; int my_i = 0;
    float wsum = 0.0f;

    #pragma unroll
    for (int it = 0; it < 8; it++) {
        float bv = -INFINITY; int bi = 0x7fffffff; float bsco = 0.0f;
        #pragma unroll
        for (int jj = 0; jj < 8; jj++) {
            if (v[jj] > bv) { bv = v[jj]; bi = lane * 8 + jj; bsco = sc[jj]; }
        }
        #pragma unroll
        for (int off = 16; off; off >>= 1) {
            float ov = __shfl_xor_sync(FULL, bv, off);
            int   oi = __shfl_xor_sync(FULL, bi, off);
            float os = __shfl_xor_sync(FULL, bsco, off);
            if (ov > bv || (ov == bv && oi < bi)) { bv = ov; bi = oi; bsco = os; }
        }
        if (lane == it) { my_w = bsco; my_i = bi; }
        if ((bi >> 3) == lane) v[bi & 7] = -INFINITY;
        wsum += bsco;
    }

    if (lane < 8) {
        out_w[(size_t)warp * 8 + lane] = (my_w / wsum) * 2.5f;
        out_i[(size_t)warp * 8 + lane] = (float)my_i;
    }
}

// ---------------------------------------------------------------------------
extern "C" void kernel_launch(void* const* d_in, const int* in_sizes, int n_in,
                              void* d_out, int out_size) {
    const float* x    = (const float*)d_in[0];   // [T, 7168]
    const float* w    = (const float*)d_in[1];   // [256, 7168]
    const float* bias = (const float*)d_in[2];   // [256]

    const int Tn = in_sizes[0] / KDIM;

    cudaFuncSetAttribute(gate_mma_gemm,
                         cudaFuncAttributeMaxDynamicSharedMemorySize, SMEM_BYTES);

    gate_wconv_kernel<<<(NEXP * KDIM + 255) / 256, 256>>>(w);

    const size_t atot = (size_t)Tn * KDIM / 4;
    gate_aconv_kernel<<<(unsigned)((atot + 255) / 256), 256>>>(x);

    dim3 grid(NEXP / BN, Tn / BM);   // (4, 128), bn fastest -> A L2 reuse
    gate_mma_gemm<<<grid, THREADS, SMEM_BYTES>>>();

    float* out_w = (float*)d_out;
    float* out_i = (float*)d_out + (size_t)Tn * 8;
    const int warps_per_block = 8;
    const int blocks = (Tn + warps_per_block - 1) / warps_per_block;
    gate_route_kernel<<<blocks, warps_per_block * 32>>>(bias, out_w, out_i, Tn);
}